// round 1
// baseline (speedup 1.0000x reference)
#include <cuda_runtime.h>
#include <cstdint>

// ---------------------------------------------------------------------------
// CCLoss: 1) nearest grid-sample pooled colors, 2) per-(b,l) top-5 smallest
// color distance over 256x256 image, 3) roll + argmin + squared-error mean.
// ---------------------------------------------------------------------------

#define IMG   256
#define NPIX  (IMG*IMG)
#define BS    8
#define LEN   64
#define KSEL  5
#define NPAIR (BS*LEN)

__device__ float g_pooled[NPAIR * 3];
__device__ unsigned long long g_top5[NPAIR * KSEL];

// ---------------------------------------------------------------------------
// Kernel 1: pooled[b][l][c] = grid_sample_nearest(ref[b], predictions[...])
// pooled[b,l] corresponds to flat row r = l*BS + b of pos_flat, whose coords
// come from predictions[r/64, r%64, 0:2], and whose image index is r%8 == b.
// ---------------------------------------------------------------------------
__global__ void pooled_kernel(const float* __restrict__ preds,
                              const float* __restrict__ ref) {
    int p = threadIdx.x;
    if (p >= NPAIR) return;
    int b = p >> 6;
    int l = p & 63;
    int r = l * BS + b;          // flat row in pos_flat
    int sb = r >> 6;             // source batch in predictions
    int sl = r & 63;             // source position in predictions
    float x = preds[(sb * LEN + sl) * 8 + 0];
    float y = preds[(sb * LEN + sl) * 8 + 1];
    float cx = x * 256.0f - 0.5f;
    float cy = y * 256.0f - 0.5f;
    int ix = (int)rintf(cx);     // rintf = round-half-even, matches jnp.rint
    int iy = (int)rintf(cy);
    float v0 = 0.0f, v1 = 0.0f, v2 = 0.0f;
    if (ix >= 0 && ix < IMG && iy >= 0 && iy < IMG) {
        int off = iy * IMG + ix;
        v0 = ref[(b * 3 + 0) * NPIX + off];
        v1 = ref[(b * 3 + 1) * NPIX + off];
        v2 = ref[(b * 3 + 2) * NPIX + off];
    }
    g_pooled[p * 3 + 0] = v0;
    g_pooled[p * 3 + 1] = v1;
    g_pooled[p * 3 + 2] = v2;
}

// ---------------------------------------------------------------------------
// Kernel 2: per (b,l) pair, find the 5 pixels of image b minimizing
//   d = (r0-p0)^2 + (r1-p1)^2 + (r2-p2)^2
// with jax.lax.top_k tie semantics: lexicographic min on (d, idx).
// Since d >= 0, the IEEE bit pattern of d is order-monotonic, so we pack
// key = (bits(d) << 32) | idx and take the 5 smallest uint64 keys.
// One CTA (256 threads) per pair; each thread scans 256 pixels via float4.
// ---------------------------------------------------------------------------
__global__ void __launch_bounds__(256) topk_kernel(const float* __restrict__ ref) {
    const int pair = blockIdx.x;
    const int b = pair >> 6;
    const int t = threadIdx.x;

    const float p0 = g_pooled[pair * 3 + 0];
    const float p1 = g_pooled[pair * 3 + 1];
    const float p2 = g_pooled[pair * 3 + 2];

    const float4* __restrict__ r0 =
        reinterpret_cast<const float4*>(ref + (size_t)(b * 3 + 0) * NPIX);
    const float4* __restrict__ r1 =
        reinterpret_cast<const float4*>(ref + (size_t)(b * 3 + 1) * NPIX);
    const float4* __restrict__ r2 =
        reinterpret_cast<const float4*>(ref + (size_t)(b * 3 + 2) * NPIX);

    // Per-thread sorted top-5 (ascending d; ties keep earlier idx because we
    // scan idx ascending within a thread and insert with strict <).
    float bd0 = 3e38f, bd1 = 3e38f, bd2 = 3e38f, bd3 = 3e38f, bd4 = 3e38f;
    int   bi0 = 0,     bi1 = 0,     bi2 = 0,     bi3 = 0,     bi4 = 0;

#define TRYINS(dv, iv) do {                                          \
    if ((dv) < bd4) {                                                \
        if ((dv) < bd3) { bd4 = bd3; bi4 = bi3;                      \
            if ((dv) < bd2) { bd3 = bd2; bi3 = bi2;                  \
                if ((dv) < bd1) { bd2 = bd1; bi2 = bi1;              \
                    if ((dv) < bd0) { bd1 = bd0; bi1 = bi0;          \
                                      bd0 = (dv); bi0 = (iv); }      \
                    else            { bd1 = (dv); bi1 = (iv); }      \
                } else { bd2 = (dv); bi2 = (iv); }                   \
            } else { bd3 = (dv); bi3 = (iv); }                       \
        } else { bd4 = (dv); bi4 = (iv); }                           \
    } } while (0)

#pragma unroll 4
    for (int i = 0; i < NPIX / 4 / 256; i++) {
        int gi = i * 256 + t;                 // float4 index (coalesced)
        float4 a  = r0[gi];
        float4 c1 = r1[gi];
        float4 c2 = r2[gi];

        float dx, dy, dz;
        dx = a.x - p0; dy = c1.x - p1; dz = c2.x - p2;
        float d0 = dx * dx + dy * dy + dz * dz;
        dx = a.y - p0; dy = c1.y - p1; dz = c2.y - p2;
        float d1 = dx * dx + dy * dy + dz * dz;
        dx = a.z - p0; dy = c1.z - p1; dz = c2.z - p2;
        float d2 = dx * dx + dy * dy + dz * dz;
        dx = a.w - p0; dy = c1.w - p1; dz = c2.w - p2;
        float d3 = dx * dx + dy * dy + dz * dz;

        float m = fminf(fminf(d0, d1), fminf(d2, d3));
        if (m < bd4) {                        // rare path
            int base = gi * 4;
            TRYINS(d0, base + 0);
            TRYINS(d1, base + 1);
            TRYINS(d2, base + 2);
            TRYINS(d3, base + 3);
        }
    }
#undef TRYINS

    // Block reduction: 256 threads x 5 candidates -> global top-5.
    __shared__ unsigned long long keys[KSEL * 256];
    __shared__ unsigned long long red[256];
    __shared__ unsigned long long winner;

    keys[0 * 256 + t] = ((unsigned long long)__float_as_uint(bd0) << 32) | (unsigned int)bi0;
    keys[1 * 256 + t] = ((unsigned long long)__float_as_uint(bd1) << 32) | (unsigned int)bi1;
    keys[2 * 256 + t] = ((unsigned long long)__float_as_uint(bd2) << 32) | (unsigned int)bi2;
    keys[3 * 256 + t] = ((unsigned long long)__float_as_uint(bd3) << 32) | (unsigned int)bi3;
    keys[4 * 256 + t] = ((unsigned long long)__float_as_uint(bd4) << 32) | (unsigned int)bi4;
    __syncthreads();

    for (int k = 0; k < KSEL; k++) {
        unsigned long long m = keys[t];
#pragma unroll
        for (int j = 1; j < KSEL; j++) {
            unsigned long long v = keys[j * 256 + t];
            if (v < m) m = v;
        }
        red[t] = m;
        __syncthreads();
        for (int s = 128; s > 0; s >>= 1) {
            if (t < s) {
                if (red[t + s] < red[t]) red[t] = red[t + s];
            }
            __syncthreads();
        }
        if (t == 0) {
            winner = red[0];
            g_top5[pair * KSEL + k] = red[0];
        }
        __syncthreads();
        unsigned long long w = winner;
#pragma unroll
        for (int j = 0; j < KSEL; j++) {
            if (keys[j * 256 + t] == w) keys[j * 256 + t] = 0xFFFFFFFFFFFFFFFFull;
        }
        __syncthreads();
    }
}

// ---------------------------------------------------------------------------
// Kernel 3: tgt coords from top-5 indices, roll along l, argmin over K
// (first-min tie break, matching jnp.argmin), squared error, mean over 504.
// ---------------------------------------------------------------------------
__global__ void loss_kernel(const float* __restrict__ preds, float* __restrict__ out) {
    int p = threadIdx.x;                      // p = b*64 + l
    int b = p >> 6;
    int l = p & 63;
    float term = 0.0f;
    if (p < NPAIR && l >= 1) {
        float px = preds[(b * LEN + l) * 8 + 0];
        float py = preds[(b * LEN + l) * 8 + 1];
        int src = b * LEN + (l - 1);          // tgt_down[b,l] = tgt[b,l-1]
        float bestD = 3e38f, bx = 0.0f, by = 0.0f;
#pragma unroll
        for (int k = 0; k < KSEL; k++) {
            unsigned int idx = (unsigned int)(g_top5[src * KSEL + k] & 0xFFFFFFFFull);
            float tx = (float)(idx & 255u) * (1.0f / 256.0f);
            float ty = (float)(idx >> 8)   * (1.0f / 256.0f);
            float dx = px - tx, dy = py - ty;
            float dd = dx * dx + dy * dy;
            if (dd < bestD) { bestD = dd; bx = tx; by = ty; }  // strict: first min wins
        }
        float ex = px - bx, ey = py - by;
        term = ex * ex + ey * ey;
    }
    __shared__ float s[512];
    s[p] = term;
    __syncthreads();
    for (int st = 256; st > 0; st >>= 1) {
        if (p < st) s[p] += s[p + st];
        __syncthreads();
    }
    if (p == 0) out[0] = s[0] / (float)(BS * (LEN - 1));
}

// ---------------------------------------------------------------------------
extern "C" void kernel_launch(void* const* d_in, const int* in_sizes, int n_in,
                              void* d_out, int out_size) {
    const float* preds = (const float*)d_in[0];   // (8, 64, 8) float32
    const float* ref   = (const float*)d_in[1];   // (8, 3, 256, 256) float32
    float* out = (float*)d_out;

    pooled_kernel<<<1, 512>>>(preds, ref);
    topk_kernel<<<NPAIR, 256>>>(ref);
    loss_kernel<<<1, 512>>>(preds, out);
}